// round 6
// baseline (speedup 1.0000x reference)
#include <cuda_runtime.h>
#include <cuda_bf16.h>
#include <cuda_fp8.h>
#include <cstdint>

#define BATCH 8192
#define DFEAT 784
#define KPAD  832          // 13 * 64 fp8 elements
#define KC    64           // fp8 elements per smem stage chunk (64B rows)
#define NC    13
#define TM    128
#define TN    128
#define STAGES 3
#define NTILE 2080         // 64*65/2 upper-triangular 128x128 tiles

#define A_STAGE_BYTES 8192          // 128 rows * 64 B
#define B_STAGE_BYTES 8192
#define STAGE_BYTES   (A_STAGE_BYTES + B_STAGE_BYTES)
#define SMEM_DYN      (STAGES * STAGE_BYTES)

__device__ __nv_fp8_e4m3 g_qn[(size_t)BATCH * KPAD];

// ---------------------------------------------------------------------------
// Kernel A: conv(2x2,s2)+bias -> groupwise 4x4 unitary -> qf
//           -> row norm -> fp8 qn scratch; linear head -> log_softmax
// ---------------------------------------------------------------------------
__global__ __launch_bounds__(256) void prep_kernel(
    const float* __restrict__ x, const float* __restrict__ conv_w,
    const float* __restrict__ conv_b, const float* __restrict__ unitary,
    const float* __restrict__ lin_w, const float* __restrict__ lin_b,
    float* __restrict__ out_logp)
{
    __shared__ float xs[784];
    __shared__ float flat[784];
    __shared__ float qf[784];
    __shared__ float cw[16];
    __shared__ float cb[4];
    __shared__ float U[16];
    __shared__ float ssw[8];
    __shared__ float wred[8][10];
    __shared__ float sinv;

    const int b = blockIdx.x;
    const int tid = threadIdx.x;
    const int lane = tid & 31;
    const int wid = tid >> 5;

    if (tid < 16)                cw[tid]      = conv_w[tid];
    if (tid >= 32 && tid < 36)   cb[tid - 32] = conv_b[tid - 32];
    if (tid >= 64 && tid < 80)   U[tid - 64]  = unitary[tid - 64];

    const float* xb = x + (size_t)b * 784;
    for (int i = tid; i < 784; i += 256) xs[i] = xb[i];
    __syncthreads();

    for (int idx = tid; idx < 784; idx += 256) {
        int o = idx / 196;
        int p = idx - o * 196;
        int i = p / 14;
        int j = p - i * 14;
        const float* xr = xs + (2 * i) * 28 + 2 * j;
        flat[idx] = cb[o] + cw[o*4+0]*xr[0]  + cw[o*4+1]*xr[1]
                          + cw[o*4+2]*xr[28] + cw[o*4+3]*xr[29];
    }
    __syncthreads();

    float ss = 0.f;
    for (int idx = tid; idx < 784; idx += 256) {
        int n4 = idx & ~3;
        int w  = idx & 3;
        float v = flat[n4+0]*U[w*4+0] + flat[n4+1]*U[w*4+1]
                + flat[n4+2]*U[w*4+2] + flat[n4+3]*U[w*4+3];
        qf[idx] = v;
        ss += v * v;
    }
#pragma unroll
    for (int o = 16; o; o >>= 1) ss += __shfl_xor_sync(0xffffffffu, ss, o);
    if (lane == 0) ssw[wid] = ss;
    __syncthreads();
    if (tid == 0) {
        float t = 0.f;
#pragma unroll
        for (int i = 0; i < 8; i++) t += ssw[i];
        sinv = 1.f / (sqrtf(t) + 1e-12f);
    }
    __syncthreads();
    const float inv = sinv;

    for (int idx = tid; idx < 784; idx += 256)
        g_qn[(size_t)b * KPAD + idx] = __nv_fp8_e4m3(qf[idx] * inv);
    if (tid < KPAD - 784)
        g_qn[(size_t)b * KPAD + 784 + tid] = __nv_fp8_e4m3(0.f);

    float part[10];
#pragma unroll
    for (int c = 0; c < 10; c++) part[c] = 0.f;
    for (int d = tid; d < 784; d += 256) {
        float v = qf[d];
#pragma unroll
        for (int c = 0; c < 10; c++) part[c] += v * lin_w[c * 784 + d];
    }
#pragma unroll
    for (int c = 0; c < 10; c++) {
        float v = part[c];
#pragma unroll
        for (int o = 16; o; o >>= 1) v += __shfl_xor_sync(0xffffffffu, v, o);
        if (lane == 0) wred[wid][c] = v;
    }
    __syncthreads();
    if (tid == 0) {
        float lg[10];
#pragma unroll
        for (int c = 0; c < 10; c++) {
            float t = lin_b[c];
#pragma unroll
            for (int w8 = 0; w8 < 8; w8++) t += wred[w8][c];
            lg[c] = t;
        }
        float mx = lg[0];
#pragma unroll
        for (int c = 1; c < 10; c++) mx = fmaxf(mx, lg[c]);
        float s = 0.f;
#pragma unroll
        for (int c = 0; c < 10; c++) s += expf(lg[c] - mx);
        float lse = mx + logf(s);
#pragma unroll
        for (int c = 0; c < 10; c++) out_logp[(size_t)b * 10 + c] = lg[c] - lse;
    }
}

// ---------------------------------------------------------------------------
// adj kernel: dense triangular grid of 128x128 tiles, 8 warps of 64x32,
// FP8 e4m3 mma.sync m16n8k32, 3-stage cp.async pipeline, 2 CTAs/SM.
// ---------------------------------------------------------------------------
__device__ __forceinline__ void ldsm4(uint32_t& r0, uint32_t& r1,
                                      uint32_t& r2, uint32_t& r3, uint32_t addr)
{
    asm volatile("ldmatrix.sync.aligned.m8n8.x4.shared.b16 {%0,%1,%2,%3}, [%4];"
                 : "=r"(r0), "=r"(r1), "=r"(r2), "=r"(r3) : "r"(addr));
}

__device__ __forceinline__ void mma_fp8(float* c, const uint32_t* a, const uint32_t* b)
{
    asm volatile("mma.sync.aligned.m16n8k32.row.col.f32.e4m3.e4m3.f32 "
                 "{%0,%1,%2,%3}, {%4,%5,%6,%7}, {%8,%9}, {%0,%1,%2,%3};"
                 : "+f"(c[0]), "+f"(c[1]), "+f"(c[2]), "+f"(c[3])
                 : "r"(a[0]), "r"(a[1]), "r"(a[2]), "r"(a[3]),
                   "r"(b[0]), "r"(b[1]));
}

__device__ __forceinline__ void cpa16(uint32_t s, const void* g) {
    asm volatile("cp.async.cg.shared.global [%0], [%1], 16;" :: "r"(s), "l"(g));
}

__global__ __launch_bounds__(256, 2) void adj_kernel(float* __restrict__ adj)
{
    // decode triangular index -> (br <= bc)
    const int i = blockIdx.x;
    int bc = (int)((sqrtf(8.0f * (float)i + 1.0f) - 1.0f) * 0.5f);
    while ((bc + 1) * (bc + 2) / 2 <= i) ++bc;
    while (bc * (bc + 1) / 2 > i) --bc;
    const int br = i - bc * (bc + 1) / 2;

    extern __shared__ char smem[];
    const uint32_t sBase = (uint32_t)__cvta_generic_to_shared(smem);

    const int tid  = threadIdx.x;
    const int lane = tid & 31;
    const int wid  = tid >> 5;
    const int wm   = wid >> 2;   // 0..1  (64 rows each)
    const int wn   = wid & 3;    // 0..3  (32 cols each)

    float acc[4][4][4];
#pragma unroll
    for (int a = 0; a < 4; a++)
#pragma unroll
        for (int j = 0; j < 4; j++)
#pragma unroll
            for (int k = 0; k < 4; k++) acc[a][j][k] = 0.f;

    const __nv_fp8_e4m3* gA = g_qn + (size_t)br * TM * KPAD;
    const __nv_fp8_e4m3* gB = g_qn + (size_t)bc * TN * KPAD;

    auto load_stage = [&](int s, int c) {
        const uint32_t sa = sBase + s * STAGE_BYTES;
        const uint32_t sb = sa + A_STAGE_BYTES;
        const __nv_fp8_e4m3* ga = gA + c * KC;
        const __nv_fp8_e4m3* gb = gB + c * KC;
#pragma unroll
        for (int t = 0; t < 2; ++t) {
            int q   = tid + t * 256;
            int row = q >> 2;
            int ch  = q & 3;                 // 16B chunk within 64B row
            int sw  = ch ^ ((row >> 1) & 3);
            uint32_t so = (uint32_t)(row * 64 + sw * 16);
            cpa16(sa + so, ga + (size_t)row * KPAD + ch * 16);
            cpa16(sb + so, gb + (size_t)row * KPAD + ch * 16);
        }
    };

    auto compute = [&](int s) {
        const uint32_t base_a = sBase + s * STAGE_BYTES;
        const uint32_t base_b = base_a + A_STAGE_BYTES;
#pragma unroll
        for (int ks = 0; ks < 2; ++ks) {     // two k32 steps per 64-elem chunk
            uint32_t a[4][4], bb[4][2];
#pragma unroll
            for (int mf = 0; mf < 4; ++mf) {
                int row = wm * 64 + mf * 16 + (lane & 15);
                int c16 = ks * 2 + (lane >> 4);          // 16B-chunk column
                int ch  = c16 ^ ((row >> 1) & 3);
                uint32_t addr = base_a + (uint32_t)(row * 64 + ch * 16);
                ldsm4(a[mf][0], a[mf][1], a[mf][2], a[mf][3], addr);
            }
#pragma unroll
            for (int nf2 = 0; nf2 < 2; ++nf2) {
                int row = wn * 32 + nf2 * 16 + ((lane >> 4) << 3) + (lane & 7);
                int c16 = ks * 2 + ((lane >> 3) & 1);
                int ch  = c16 ^ ((row >> 1) & 3);
                uint32_t addr = base_b + (uint32_t)(row * 64 + ch * 16);
                ldsm4(bb[nf2*2][0], bb[nf2*2][1], bb[nf2*2+1][0], bb[nf2*2+1][1], addr);
            }
#pragma unroll
            for (int mf = 0; mf < 4; ++mf)
#pragma unroll
                for (int nf = 0; nf < 4; ++nf)
                    mma_fp8(acc[mf][nf], a[mf], bb[nf]);
        }
    };

    load_stage(0, 0);
    asm volatile("cp.async.commit_group;");
    load_stage(1, 1);
    asm volatile("cp.async.commit_group;");

#pragma unroll 1
    for (int c = 0; c < NC; ++c) {
        if (c < NC - 1) asm volatile("cp.async.wait_group 1;");
        else            asm volatile("cp.async.wait_group 0;");
        __syncthreads();
        if (c + 2 < NC) {
            load_stage((c + 2) % STAGES, c + 2);
            asm volatile("cp.async.commit_group;");
        }
        compute(c % STAGES);
    }

    // epilogue: fid = acc^2, threshold, no self edges; mirror for br<bc
    const int g   = lane >> 2;
    const int tig = lane & 3;
#pragma unroll
    for (int mf = 0; mf < 4; ++mf) {
        const int r0 = br * TM + wm * 64 + mf * 16 + g;
#pragma unroll
        for (int nf = 0; nf < 4; ++nf) {
            const int c0 = bc * TN + wn * 32 + nf * 8 + tig * 2;
            float f0 = acc[mf][nf][0], f1 = acc[mf][nf][1];
            float f2 = acc[mf][nf][2], f3 = acc[mf][nf][3];
            float v0 = (f0 * f0 >= 0.9f && r0     != c0    ) ? 1.f : 0.f;
            float v1 = (f1 * f1 >= 0.9f && r0     != c0 + 1) ? 1.f : 0.f;
            float v2 = (f2 * f2 >= 0.9f && r0 + 8 != c0    ) ? 1.f : 0.f;
            float v3 = (f3 * f3 >= 0.9f && r0 + 8 != c0 + 1) ? 1.f : 0.f;
            *reinterpret_cast<float2*>(&adj[(size_t)r0 * BATCH + c0]) =
                make_float2(v0, v1);
            *reinterpret_cast<float2*>(&adj[(size_t)(r0 + 8) * BATCH + c0]) =
                make_float2(v2, v3);
            if (br != bc) {
                adj[(size_t)c0       * BATCH + r0]     = v0;
                adj[(size_t)(c0 + 1) * BATCH + r0]     = v1;
                adj[(size_t)c0       * BATCH + r0 + 8] = v2;
                adj[(size_t)(c0 + 1) * BATCH + r0 + 8] = v3;
            }
        }
    }
}

// ---------------------------------------------------------------------------
extern "C" void kernel_launch(void* const* d_in, const int* in_sizes, int n_in,
                              void* d_out, int out_size)
{
    const float* x       = (const float*)d_in[0];
    const float* conv_w  = (const float*)d_in[1];
    const float* conv_b  = (const float*)d_in[2];
    const float* unitary = (const float*)d_in[3];
    const float* lin_w   = (const float*)d_in[4];
    const float* lin_b   = (const float*)d_in[5];
    float* out = (float*)d_out;

    prep_kernel<<<BATCH, 256>>>(x, conv_w, conv_b, unitary, lin_w, lin_b, out);

    cudaFuncSetAttribute(adj_kernel, cudaFuncAttributeMaxDynamicSharedMemorySize, SMEM_DYN);
    adj_kernel<<<NTILE, 256, SMEM_DYN>>>(out + (size_t)BATCH * 10);
}

// round 7
// speedup vs baseline: 1.0735x; 1.0735x over previous
#include <cuda_runtime.h>
#include <cuda_bf16.h>
#include <cstdint>

#define BATCH 8192
#define DFEAT 784
#define KPAD  800          // 25 * 32
#define KC    32
#define NC    25
#define TM    128
#define TN    128
#define STAGES 3
#define NTILE 2080         // 64*65/2 upper-triangular 128x128 tiles

#define A_STAGE_BYTES 8192          // 128 rows * 64 B
#define B_STAGE_BYTES 8192
#define STAGE_BYTES   (A_STAGE_BYTES + B_STAGE_BYTES)
#define SMEM_DYN      (STAGES * STAGE_BYTES)

__device__ __nv_bfloat16 g_qn[(size_t)BATCH * KPAD];

// ---------------------------------------------------------------------------
// Kernel A (warp-per-image): conv(2x2,s2)+bias -> groupwise 4x4 unitary
//  -> row norm -> bf16 qn scratch; linear head (lin_w in smem) -> log_softmax
// 1024 CTAs x 8 warps; each warp owns one image; no block syncs in main path.
// ---------------------------------------------------------------------------
__global__ __launch_bounds__(256) void prep_kernel(
    const float* __restrict__ x, const float* __restrict__ conv_w,
    const float* __restrict__ conv_b, const float* __restrict__ unitary,
    const float* __restrict__ lin_w, const float* __restrict__ lin_b,
    float* __restrict__ out_logp)
{
    __shared__ float lw[7840];        // 10 x 784 linear weights
    __shared__ float xs[8][784];      // per-warp image buffer
    __shared__ float cw[16];
    __shared__ float cb[4];
    __shared__ float U[16];
    __shared__ float lb[10];

    const int tid  = threadIdx.x;
    const int lane = tid & 31;
    const int wid  = tid >> 5;

    for (int i = tid; i < 7840; i += 256) lw[i] = lin_w[i];
    if (tid < 16)               cw[tid]      = conv_w[tid];
    if (tid >= 32 && tid < 36)  cb[tid - 32] = conv_b[tid - 32];
    if (tid >= 64 && tid < 80)  U[tid - 64]  = unitary[tid - 64];
    if (tid >= 96 && tid < 106) lb[tid - 96] = lin_b[tid - 96];
    __syncthreads();

    const int b = blockIdx.x * 8 + wid;

    // load image (784 floats = 196 float4, coalesced within warp)
    {
        const float4* x4 = reinterpret_cast<const float4*>(x + (size_t)b * 784);
        float4* s4 = reinterpret_cast<float4*>(xs[wid]);
        for (int i = lane; i < 196; i += 32) s4[i] = x4[i];
    }
    __syncwarp();

    // conv + unitary, values kept in registers: group g covers flat[4g..4g+3]
    float qv[7][4];
    float ss = 0.f;
    {
        int ng = 0;
        for (int g = lane; g < 196; g += 32, ++ng) {
            const int o  = (4 * g) / 196;        // channel (196 % 4 == 0)
            const int p0 = 4 * g - o * 196;
            float f[4];
#pragma unroll
            for (int u = 0; u < 4; ++u) {
                int p = p0 + u;
                int i = p / 14;
                int j = p - 14 * i;
                const float* xr = xs[wid] + (2 * i) * 28 + 2 * j;
                f[u] = cb[o] + cw[o*4+0]*xr[0]  + cw[o*4+1]*xr[1]
                             + cw[o*4+2]*xr[28] + cw[o*4+3]*xr[29];
            }
#pragma unroll
            for (int w = 0; w < 4; ++w) {
                float v = f[0]*U[w*4+0] + f[1]*U[w*4+1]
                        + f[2]*U[w*4+2] + f[3]*U[w*4+3];
                qv[ng][w] = v;
                ss += v * v;
            }
        }
    }
#pragma unroll
    for (int o = 16; o; o >>= 1) ss += __shfl_xor_sync(0xffffffffu, ss, o);
    const float inv = 1.f / (sqrtf(ss) + 1e-12f);

    // bf16 normalized store, 8B per group
    {
        uint2* dst = reinterpret_cast<uint2*>(g_qn + (size_t)b * KPAD);
        int ng = 0;
        for (int g = lane; g < 196; g += 32, ++ng) {
            __nv_bfloat162 lo = __floats2bfloat162_rn(qv[ng][0]*inv, qv[ng][1]*inv);
            __nv_bfloat162 hi = __floats2bfloat162_rn(qv[ng][2]*inv, qv[ng][3]*inv);
            uint2 pk;
            pk.x = *reinterpret_cast<uint32_t*>(&lo);
            pk.y = *reinterpret_cast<uint32_t*>(&hi);
            dst[g] = pk;
        }
        if (lane < 4) {   // pad 784..799 with zeros (4 lanes x 4 elems)
            uint2 z; z.x = 0u; z.y = 0u;
            dst[196 + lane] = z;
        }
    }

    // linear head from registers + smem weights
    float part[10];
#pragma unroll
    for (int c = 0; c < 10; ++c) part[c] = 0.f;
    {
        int ng = 0;
        for (int g = lane; g < 196; g += 32, ++ng) {
#pragma unroll
            for (int c = 0; c < 10; ++c) {
                const float4 w4 = *reinterpret_cast<const float4*>(lw + c * 784 + 4 * g);
                part[c] += qv[ng][0]*w4.x + qv[ng][1]*w4.y
                         + qv[ng][2]*w4.z + qv[ng][3]*w4.w;
            }
        }
    }
#pragma unroll
    for (int c = 0; c < 10; ++c) {
#pragma unroll
        for (int o = 16; o; o >>= 1)
            part[c] += __shfl_xor_sync(0xffffffffu, part[c], o);
    }
    if (lane == 0) {
        float lg[10];
#pragma unroll
        for (int c = 0; c < 10; ++c) lg[c] = part[c] + lb[c];
        float mx = lg[0];
#pragma unroll
        for (int c = 1; c < 10; ++c) mx = fmaxf(mx, lg[c]);
        float s = 0.f;
#pragma unroll
        for (int c = 0; c < 10; ++c) s += expf(lg[c] - mx);
        float lse = mx + logf(s);
#pragma unroll
        for (int c = 0; c < 10; ++c) out_logp[(size_t)b * 10 + c] = lg[c] - lse;
    }
}

// ---------------------------------------------------------------------------
// adj kernel (R5 best): dense triangular grid of 128x128 tiles, 8 warps of
// 64x32, mma.sync bf16, 3-stage cp.async pipeline, 2 CTAs/SM.
// ---------------------------------------------------------------------------
__device__ __forceinline__ void ldsm4(uint32_t& r0, uint32_t& r1,
                                      uint32_t& r2, uint32_t& r3, uint32_t addr)
{
    asm volatile("ldmatrix.sync.aligned.m8n8.x4.shared.b16 {%0,%1,%2,%3}, [%4];"
                 : "=r"(r0), "=r"(r1), "=r"(r2), "=r"(r3) : "r"(addr));
}

__device__ __forceinline__ void mma16816(float* c, const uint32_t* a, const uint32_t* b)
{
    asm volatile("mma.sync.aligned.m16n8k16.row.col.f32.bf16.bf16.f32 "
                 "{%0,%1,%2,%3}, {%4,%5,%6,%7}, {%8,%9}, {%0,%1,%2,%3};"
                 : "+f"(c[0]), "+f"(c[1]), "+f"(c[2]), "+f"(c[3])
                 : "r"(a[0]), "r"(a[1]), "r"(a[2]), "r"(a[3]),
                   "r"(b[0]), "r"(b[1]));
}

__device__ __forceinline__ void cpa16(uint32_t s, const void* g) {
    asm volatile("cp.async.cg.shared.global [%0], [%1], 16;" :: "r"(s), "l"(g));
}

__global__ __launch_bounds__(256, 2) void adj_kernel(float* __restrict__ adj)
{
    // decode triangular index -> (br <= bc)
    const int i = blockIdx.x;
    int bc = (int)((sqrtf(8.0f * (float)i + 1.0f) - 1.0f) * 0.5f);
    while ((bc + 1) * (bc + 2) / 2 <= i) ++bc;
    while (bc * (bc + 1) / 2 > i) --bc;
    const int br = i - bc * (bc + 1) / 2;

    extern __shared__ char smem[];
    const uint32_t sBase = (uint32_t)__cvta_generic_to_shared(smem);

    const int tid  = threadIdx.x;
    const int lane = tid & 31;
    const int wid  = tid >> 5;
    const int wm   = wid >> 2;   // 0..1  (64 rows each)
    const int wn   = wid & 3;    // 0..3  (32 cols each)

    float acc[4][4][4];
#pragma unroll
    for (int a = 0; a < 4; a++)
#pragma unroll
        for (int j = 0; j < 4; j++)
#pragma unroll
            for (int k = 0; k < 4; k++) acc[a][j][k] = 0.f;

    const __nv_bfloat16* gA = g_qn + (size_t)br * TM * KPAD;
    const __nv_bfloat16* gB = g_qn + (size_t)bc * TN * KPAD;

    auto load_stage = [&](int s, int c) {
        const uint32_t sa = sBase + s * STAGE_BYTES;
        const uint32_t sb = sa + A_STAGE_BYTES;
        const __nv_bfloat16* ga = gA + c * KC;
        const __nv_bfloat16* gb = gB + c * KC;
#pragma unroll
        for (int t = 0; t < 2; ++t) {
            int q   = tid + t * 256;
            int row = q >> 2;
            int ch  = q & 3;
            int sw  = ch ^ ((row >> 1) & 3);
            uint32_t so = (uint32_t)(row * 64 + sw * 16);
            cpa16(sa + so, ga + (size_t)row * KPAD + ch * 8);
            cpa16(sb + so, gb + (size_t)row * KPAD + ch * 8);
        }
    };

    auto compute = [&](int s) {
        const uint32_t base_a = sBase + s * STAGE_BYTES;
        const uint32_t base_b = base_a + A_STAGE_BYTES;
#pragma unroll
        for (int ks = 0; ks < KC; ks += 16) {
            uint32_t a[4][4], bb[4][2];
#pragma unroll
            for (int mf = 0; mf < 4; ++mf) {
                int row = wm * 64 + mf * 16 + (lane & 15);
                int col = ks + ((lane >> 4) << 3);
                int ch  = (col >> 3) ^ ((row >> 1) & 3);
                uint32_t addr = base_a + (uint32_t)((row * 32 + ch * 8) * 2);
                ldsm4(a[mf][0], a[mf][1], a[mf][2], a[mf][3], addr);
            }
#pragma unroll
            for (int nf2 = 0; nf2 < 2; ++nf2) {
                int row = wn * 32 + nf2 * 16 + ((lane >> 4) << 3) + (lane & 7);
                int col = ks + ((lane >> 3) & 1) * 8;
                int ch  = (col >> 3) ^ ((row >> 1) & 3);
                uint32_t addr = base_b + (uint32_t)((row * 32 + ch * 8) * 2);
                ldsm4(bb[nf2*2][0], bb[nf2*2][1], bb[nf2*2+1][0], bb[nf2*2+1][1], addr);
            }
#pragma unroll
            for (int mf = 0; mf < 4; ++mf)
#pragma unroll
                for (int nf = 0; nf < 4; ++nf)
                    mma16816(acc[mf][nf], a[mf], bb[nf]);
        }
    };

    load_stage(0, 0);
    asm volatile("cp.async.commit_group;");
    load_stage(1, 1);
    asm volatile("cp.async.commit_group;");

#pragma unroll 1
    for (int c = 0; c < NC; ++c) {
        if (c < NC - 1) asm volatile("cp.async.wait_group 1;");
        else            asm volatile("cp.async.wait_group 0;");
        __syncthreads();
        if (c + 2 < NC) {
            load_stage((c + 2) % STAGES, c + 2);
            asm volatile("cp.async.commit_group;");
        }
        compute(c % STAGES);
    }

    // epilogue: fid = acc^2, threshold, no self edges; mirror for br<bc
    const int g   = lane >> 2;
    const int tig = lane & 3;
#pragma unroll
    for (int mf = 0; mf < 4; ++mf) {
        const int r0 = br * TM + wm * 64 + mf * 16 + g;
#pragma unroll
        for (int nf = 0; nf < 4; ++nf) {
            const int c0 = bc * TN + wn * 32 + nf * 8 + tig * 2;
            float f0 = acc[mf][nf][0], f1 = acc[mf][nf][1];
            float f2 = acc[mf][nf][2], f3 = acc[mf][nf][3];
            float v0 = (f0 * f0 >= 0.9f && r0     != c0    ) ? 1.f : 0.f;
            float v1 = (f1 * f1 >= 0.9f && r0     != c0 + 1) ? 1.f : 0.f;
            float v2 = (f2 * f2 >= 0.9f && r0 + 8 != c0    ) ? 1.f : 0.f;
            float v3 = (f3 * f3 >= 0.9f && r0 + 8 != c0 + 1) ? 1.f : 0.f;
            *reinterpret_cast<float2*>(&adj[(size_t)r0 * BATCH + c0]) =
                make_float2(v0, v1);
            *reinterpret_cast<float2*>(&adj[(size_t)(r0 + 8) * BATCH + c0]) =
                make_float2(v2, v3);
            if (br != bc) {
                adj[(size_t)c0       * BATCH + r0]     = v0;
                adj[(size_t)(c0 + 1) * BATCH + r0]     = v1;
                adj[(size_t)c0       * BATCH + r0 + 8] = v2;
                adj[(size_t)(c0 + 1) * BATCH + r0 + 8] = v3;
            }
        }
    }
}

// ---------------------------------------------------------------------------
extern "C" void kernel_launch(void* const* d_in, const int* in_sizes, int n_in,
                              void* d_out, int out_size)
{
    const float* x       = (const float*)d_in[0];
    const float* conv_w  = (const float*)d_in[1];
    const float* conv_b  = (const float*)d_in[2];
    const float* unitary = (const float*)d_in[3];
    const float* lin_w   = (const float*)d_in[4];
    const float* lin_b   = (const float*)d_in[5];
    float* out = (float*)d_out;

    prep_kernel<<<BATCH / 8, 256>>>(x, conv_w, conv_b, unitary, lin_w, lin_b, out);

    cudaFuncSetAttribute(adj_kernel, cudaFuncAttributeMaxDynamicSharedMemorySize, SMEM_DYN);
    adj_kernel<<<NTILE, 256, SMEM_DYN>>>(out + (size_t)BATCH * 10);
}